// round 1
// baseline (speedup 1.0000x reference)
#include <cuda_runtime.h>
#include <math.h>

#define D_MODEL 2048
#define SEQ     1024
#define BATCH   4
#define NH      32
#define NKV     8
#define HD      64

// Scratch (device globals — no allocations allowed)
__device__ float g_Q[BATCH * NH  * SEQ * HD];   // (B,H,S,HD)
__device__ float g_K[BATCH * NKV * SEQ * HD];   // (B,KV,S,HD)
__device__ float g_V[BATCH * NKV * SEQ * HD];   // (B,KV,S,HD)
__device__ float g_A[BATCH * SEQ * D_MODEL];    // attention out, (B*S, H*HD)

// ============================================================================
// SGEMM 128x128x8 tile, 256 threads, 8x8 per thread.
// C[m][n] = dot(x[m,:], W[n,:])  (W row-major, N rows x K cols)
// ============================================================================

// Fused QKV projection + head-indexed RoPE epilogue.
// N space: [0,2048) -> wq, [2048,2560) -> wk, [2560,3072) -> wv
__global__ __launch_bounds__(256) void qkv_rope_kernel(
    const float* __restrict__ x,
    const float* __restrict__ wq,
    const float* __restrict__ wk,
    const float* __restrict__ wv,
    const float* __restrict__ fcos,
    const float* __restrict__ fsin)
{
    __shared__ float As[8][128];
    __shared__ float Bs[8][128];

    const int tid = threadIdx.x;
    const int m0 = blockIdx.y * 128;
    const int n0 = blockIdx.x * 128;

    const float* W;
    int nbase, kind;
    if (n0 < 2048)      { W = wq; nbase = n0;        kind = 0; }
    else if (n0 < 2560) { W = wk; nbase = n0 - 2048; kind = 1; }
    else                { W = wv; nbase = n0 - 2560; kind = 2; }

    const int lr = tid >> 1;        // 0..127 (load row)
    const int lc = (tid & 1) * 4;   // 0 or 4 (load col within 8)
    const int ty = tid >> 4;        // 0..15
    const int tx = tid & 15;        // 0..15

    float acc[8][8];
    #pragma unroll
    for (int i = 0; i < 8; i++)
        #pragma unroll
        for (int j = 0; j < 8; j++) acc[i][j] = 0.0f;

    const float* aptr = x + (size_t)(m0 + lr) * D_MODEL + lc;
    const float* bptr = W + (size_t)(nbase + lr) * D_MODEL + lc;

    for (int k0 = 0; k0 < D_MODEL; k0 += 8) {
        float4 av = *(const float4*)(aptr + k0);
        float4 bv = *(const float4*)(bptr + k0);
        As[lc + 0][lr] = av.x; As[lc + 1][lr] = av.y;
        As[lc + 2][lr] = av.z; As[lc + 3][lr] = av.w;
        Bs[lc + 0][lr] = bv.x; Bs[lc + 1][lr] = bv.y;
        Bs[lc + 2][lr] = bv.z; Bs[lc + 3][lr] = bv.w;
        __syncthreads();
        #pragma unroll
        for (int kk = 0; kk < 8; kk++) {
            float a[8], b[8];
            #pragma unroll
            for (int i = 0; i < 8; i++) a[i] = As[kk][ty * 8 + i];
            #pragma unroll
            for (int j = 0; j < 8; j++) b[j] = Bs[kk][tx * 8 + j];
            #pragma unroll
            for (int i = 0; i < 8; i++)
                #pragma unroll
                for (int j = 0; j < 8; j++)
                    acc[i][j] = fmaf(a[i], b[j], acc[i][j]);
        }
        __syncthreads();
    }

    // Epilogue: RoPE (indexed by HEAD, per the reference's quirk) + scatter.
    #pragma unroll
    for (int i = 0; i < 8; i++) {
        const int m = m0 + ty * 8 + i;
        const int bb = m >> 10;          // batch
        const int s  = m & 1023;         // seq pos
        #pragma unroll
        for (int j = 0; j < 8; j += 2) {
            const int nb = nbase + tx * 8 + j;   // row within weight matrix
            const int h = nb >> 6;
            const int d = nb & 63;
            float v0 = acc[i][j], v1 = acc[i][j + 1];
            if (kind == 2) {
                float* dst = g_V + ((size_t)(bb * NKV + h) * SEQ + s) * HD + d;
                dst[0] = v0; dst[1] = v1;
            } else {
                const int p = d >> 1;
                float c  = fcos[h * (HD / 2) + p];
                float sn = fsin[h * (HD / 2) + p];
                float o0 = v0 * c - v1 * sn;
                float o1 = v0 * sn + v1 * c;
                float* dst = (kind == 0)
                    ? g_Q + ((size_t)(bb * NH  + h) * SEQ + s) * HD + d
                    : g_K + ((size_t)(bb * NKV + h) * SEQ + s) * HD + d;
                dst[0] = o0; dst[1] = o1;
            }
        }
    }
}

// O-projection: out[m][n] = dot(g_A[m,:], wo[n,:])
__global__ __launch_bounds__(256) void oproj_kernel(
    const float* __restrict__ wo, float* __restrict__ out)
{
    __shared__ float As[8][128];
    __shared__ float Bs[8][128];

    const int tid = threadIdx.x;
    const int m0 = blockIdx.y * 128;
    const int n0 = blockIdx.x * 128;

    const int lr = tid >> 1;
    const int lc = (tid & 1) * 4;
    const int ty = tid >> 4;
    const int tx = tid & 15;

    float acc[8][8];
    #pragma unroll
    for (int i = 0; i < 8; i++)
        #pragma unroll
        for (int j = 0; j < 8; j++) acc[i][j] = 0.0f;

    const float* aptr = g_A + (size_t)(m0 + lr) * D_MODEL + lc;
    const float* bptr = wo  + (size_t)(n0 + lr) * D_MODEL + lc;

    for (int k0 = 0; k0 < D_MODEL; k0 += 8) {
        float4 av = *(const float4*)(aptr + k0);
        float4 bv = *(const float4*)(bptr + k0);
        As[lc + 0][lr] = av.x; As[lc + 1][lr] = av.y;
        As[lc + 2][lr] = av.z; As[lc + 3][lr] = av.w;
        Bs[lc + 0][lr] = bv.x; Bs[lc + 1][lr] = bv.y;
        Bs[lc + 2][lr] = bv.z; Bs[lc + 3][lr] = bv.w;
        __syncthreads();
        #pragma unroll
        for (int kk = 0; kk < 8; kk++) {
            float a[8], b[8];
            #pragma unroll
            for (int i = 0; i < 8; i++) a[i] = As[kk][ty * 8 + i];
            #pragma unroll
            for (int j = 0; j < 8; j++) b[j] = Bs[kk][tx * 8 + j];
            #pragma unroll
            for (int i = 0; i < 8; i++)
                #pragma unroll
                for (int j = 0; j < 8; j++)
                    acc[i][j] = fmaf(a[i], b[j], acc[i][j]);
        }
        __syncthreads();
    }

    #pragma unroll
    for (int i = 0; i < 8; i++) {
        const int m = m0 + ty * 8 + i;
        float4 r0, r1;
        r0.x = acc[i][0]; r0.y = acc[i][1]; r0.z = acc[i][2]; r0.w = acc[i][3];
        r1.x = acc[i][4]; r1.y = acc[i][5]; r1.z = acc[i][6]; r1.w = acc[i][7];
        float* dst = out + (size_t)m * D_MODEL + n0 + tx * 8;
        *(float4*)(dst)     = r0;
        *(float4*)(dst + 4) = r1;
    }
}

// ============================================================================
// Flash-style causal attention.
// Grid: (qtile=16, h=32, b=4). 256 threads. Each block: 64 q rows x HD=64.
// Thread t: q-row = t/4, owns d-columns [(t%4)*16, +16).
// ============================================================================

#define ATT_STR 68   // smem row stride (floats), keeps float4 alignment, avoids conflicts
#define ATT_SMEM (3 * 64 * ATT_STR * 4)

__global__ __launch_bounds__(256) void attn_kernel()
{
    extern __shared__ float sm[];
    float* Ks = sm;
    float* Vs = sm + 64 * ATT_STR;
    float* Ps = sm + 2 * 64 * ATT_STR;   // reused: Q staging, then scores/probs

    const int tid   = threadIdx.x;
    const int qtile = blockIdx.x;
    const int h     = blockIdx.y;
    const int b     = blockIdx.z;
    const int hk    = h >> 2;            // GQA: kv head = h / (H/KV)

    const int qr = tid >> 2;             // 0..63 (q row in tile)
    const int qu = tid & 3;              // 0..3  (column quarter / k quarter)
    const int qgl = qtile * 64 + qr;     // global q position

    // --- Stage Q tile into Ps, then pull my row into registers ---
    {
        const float* src = g_Q + ((size_t)(b * NH + h) * SEQ + qtile * 64) * HD;
        #pragma unroll
        for (int i = 0; i < 4; i++) {
            int f4 = tid + 256 * i;          // 0..1023 float4s
            int row = f4 >> 4;
            int col = (f4 & 15) * 4;
            *(float4*)&Ps[row * ATT_STR + col] = ((const float4*)src)[f4];
        }
    }
    __syncthreads();
    float q_reg[64];
    #pragma unroll
    for (int d4 = 0; d4 < 16; d4++) {
        float4 v = *(const float4*)&Ps[qr * ATT_STR + d4 * 4];
        q_reg[d4 * 4 + 0] = v.x; q_reg[d4 * 4 + 1] = v.y;
        q_reg[d4 * 4 + 2] = v.z; q_reg[d4 * 4 + 3] = v.w;
    }
    __syncthreads();

    float acc[16];
    #pragma unroll
    for (int j = 0; j < 16; j++) acc[j] = 0.0f;
    float mrow = -INFINITY;
    float lrow = 0.0f;

    const int ntiles = qtile + 1;        // causal
    const float* kbase = g_K + ((size_t)(b * NKV + hk) * SEQ) * HD;
    const float* vbase = g_V + ((size_t)(b * NKV + hk) * SEQ) * HD;

    for (int t = 0; t < ntiles; t++) {
        // Load K and V tiles (64x64 each), contiguous 4096 floats.
        {
            const float* ksrc = kbase + (size_t)t * 64 * HD;
            const float* vsrc = vbase + (size_t)t * 64 * HD;
            #pragma unroll
            for (int i = 0; i < 4; i++) {
                int f4 = tid + 256 * i;
                int row = f4 >> 4;
                int col = (f4 & 15) * 4;
                *(float4*)&Ks[row * ATT_STR + col] = ((const float4*)ksrc)[f4];
                *(float4*)&Vs[row * ATT_STR + col] = ((const float4*)vsrc)[f4];
            }
        }
        __syncthreads();

        // Phase A: raw scores for my 16 k-columns -> Ps, track tile max.
        float tmax = -INFINITY;
        for (int kk = 0; kk < 16; kk++) {
            const int k = qu * 16 + kk;
            const float4* kr4 = (const float4*)&Ks[k * ATT_STR];
            float s = 0.0f;
            #pragma unroll
            for (int d4 = 0; d4 < 16; d4++) {
                float4 kv = kr4[d4];
                s = fmaf(q_reg[d4 * 4 + 0], kv.x, s);
                s = fmaf(q_reg[d4 * 4 + 1], kv.y, s);
                s = fmaf(q_reg[d4 * 4 + 2], kv.z, s);
                s = fmaf(q_reg[d4 * 4 + 3], kv.w, s);
            }
            s *= 0.125f;                           // 1/sqrt(64)
            const int kgl = t * 64 + k;
            if (kgl > qgl) s = -INFINITY;          // causal
            Ps[qr * ATT_STR + k] = s;
            tmax = fmaxf(tmax, s);
        }
        // Row max across the 4 threads sharing this q-row.
        tmax = fmaxf(tmax, __shfl_xor_sync(0xFFFFFFFFu, tmax, 1));
        tmax = fmaxf(tmax, __shfl_xor_sync(0xFFFFFFFFu, tmax, 2));

        const float mnew = fmaxf(mrow, tmax);
        const float corr = __expf(mrow - mnew);

        // Phase B: exponentiate my 16 scores in place, partial sum.
        float psum = 0.0f;
        for (int kk = 0; kk < 16; kk++) {
            const int k = qu * 16 + kk;
            float p = __expf(Ps[qr * ATT_STR + k] - mnew);
            Ps[qr * ATT_STR + k] = p;
            psum += p;
        }
        psum += __shfl_xor_sync(0xFFFFFFFFu, psum, 1);
        psum += __shfl_xor_sync(0xFFFFFFFFu, psum, 2);

        lrow = lrow * corr + psum;
        mrow = mnew;
        #pragma unroll
        for (int j = 0; j < 16; j++) acc[j] *= corr;
        __syncthreads();   // Ps (probs) visible to all 4 row-threads

        // P @ V: my 16 d-columns.
        for (int k = 0; k < 64; k++) {
            const float p = Ps[qr * ATT_STR + k];
            const float4* vr = (const float4*)&Vs[k * ATT_STR + qu * 16];
            #pragma unroll
            for (int j4 = 0; j4 < 4; j4++) {
                float4 v = vr[j4];
                acc[j4 * 4 + 0] = fmaf(p, v.x, acc[j4 * 4 + 0]);
                acc[j4 * 4 + 1] = fmaf(p, v.y, acc[j4 * 4 + 1]);
                acc[j4 * 4 + 2] = fmaf(p, v.z, acc[j4 * 4 + 2]);
                acc[j4 * 4 + 3] = fmaf(p, v.w, acc[j4 * 4 + 3]);
            }
        }
        __syncthreads();   // done with Ks/Vs/Ps; safe to reload next tile
    }

    // Normalize and write to g_A as (B*S, H*HD).
    const float inv = 1.0f / lrow;
    float* dst = g_A + ((size_t)b * SEQ + qgl) * D_MODEL + h * HD + qu * 16;
    #pragma unroll
    for (int j4 = 0; j4 < 4; j4++) {
        float4 v;
        v.x = acc[j4 * 4 + 0] * inv;
        v.y = acc[j4 * 4 + 1] * inv;
        v.z = acc[j4 * 4 + 2] * inv;
        v.w = acc[j4 * 4 + 3] * inv;
        *(float4*)(dst + j4 * 4) = v;
    }
}

// ============================================================================
// Launch
// ============================================================================

extern "C" void kernel_launch(void* const* d_in, const int* in_sizes, int n_in,
                              void* d_out, int out_size)
{
    (void)in_sizes; (void)n_in; (void)out_size;
    const float* x    = (const float*)d_in[0];
    const float* fcos = (const float*)d_in[1];
    const float* fsin = (const float*)d_in[2];
    // d_in[3] = mask (provably causal; computed by predicate instead)
    const float* wq   = (const float*)d_in[4];
    const float* wk   = (const float*)d_in[5];
    const float* wv   = (const float*)d_in[6];
    const float* wo   = (const float*)d_in[7];
    float* out = (float*)d_out;

    cudaFuncSetAttribute(attn_kernel,
                         cudaFuncAttributeMaxDynamicSharedMemorySize, ATT_SMEM);

    dim3 g1(3072 / 128, 4096 / 128);
    qkv_rope_kernel<<<g1, 256>>>(x, wq, wk, wv, fcos, fsin);

    dim3 g2(SEQ / 64, NH, BATCH);
    attn_kernel<<<g2, 256, ATT_SMEM>>>();

    dim3 g3(2048 / 128, 4096 / 128);
    oproj_kernel<<<g3, 256>>>(wo, out);
}

// round 4
// speedup vs baseline: 1.3756x; 1.3756x over previous
#include <cuda_runtime.h>
#include <cuda_bf16.h>
#include <math.h>
#include <stdint.h>

#define D_MODEL 2048
#define SEQ     1024
#define BATCH   4
#define NH      32
#define NKV     8
#define HD      64

// ---------------------------------------------------------------------------
// Device-global scratch (no runtime allocation allowed)
// ---------------------------------------------------------------------------
__device__ float g_Q[BATCH * NH  * SEQ * HD];   // (B,H,S,HD) fp32 post-RoPE
__device__ float g_K[BATCH * NKV * SEQ * HD];
__device__ float g_V[BATCH * NKV * SEQ * HD];

// split-bf16 operands
__device__ __nv_bfloat16 g_x_hi[4096 * 2048], g_x_lo[4096 * 2048];
__device__ __nv_bfloat16 g_w_hi[3072 * 2048], g_w_lo[3072 * 2048];   // [wq;wk;wv]
__device__ __nv_bfloat16 g_wo_hi[2048 * 2048], g_wo_lo[2048 * 2048];
__device__ __nv_bfloat16 g_a_hi[4096 * 2048], g_a_lo[4096 * 2048];   // attn out

// ---------------------------------------------------------------------------
// helpers
// ---------------------------------------------------------------------------
__device__ __forceinline__ uint32_t smem_u32(const void* p) {
    uint32_t a;
    asm("{ .reg .u64 t; cvta.to.shared.u64 t, %1; cvt.u32.u64 %0, t; }"
        : "=r"(a) : "l"(p));
    return a;
}

// 128-row x 32-col bf16 tile: 64B logical rows packed 2-per-128B line,
// 16B chunks XOR-swizzled for conflict-free ldmatrix.
__device__ __forceinline__ uint32_t tile_off(int row, int chunk) {
    return (uint32_t)(((row >> 1) * 128) + ((row & 1) * 64) +
                      (((chunk ^ ((row >> 1) & 3))) << 4));
}

__device__ __forceinline__ void cp16(uint32_t dst, const __nv_bfloat16* src) {
    asm volatile("cp.async.cg.shared.global [%0], [%1], 16;"
                 :: "r"(dst), "l"(__cvta_generic_to_global(src)));
}
#define CP_COMMIT() asm volatile("cp.async.commit_group;" ::: "memory")
#define CP_WAIT1()  asm volatile("cp.async.wait_group 1;" ::: "memory")

__device__ __forceinline__ void ldmx4(uint32_t* r, uint32_t addr) {
    asm volatile("ldmatrix.sync.aligned.m8n8.x4.shared.b16 {%0,%1,%2,%3}, [%4];"
                 : "=r"(r[0]), "=r"(r[1]), "=r"(r[2]), "=r"(r[3]) : "r"(addr));
}
__device__ __forceinline__ void mma16816(float* c, const uint32_t* a,
                                         uint32_t b0, uint32_t b1) {
    asm volatile(
        "mma.sync.aligned.m16n8k16.row.col.f32.bf16.bf16.f32 "
        "{%0,%1,%2,%3}, {%4,%5,%6,%7}, {%8,%9}, {%0,%1,%2,%3};"
        : "+f"(c[0]), "+f"(c[1]), "+f"(c[2]), "+f"(c[3])
        : "r"(a[0]), "r"(a[1]), "r"(a[2]), "r"(a[3]), "r"(b0), "r"(b1));
}

// ---------------------------------------------------------------------------
// fp32 -> (hi, lo) bf16 split conversion of all GEMM operands
// ---------------------------------------------------------------------------
#define NX   (4096 * 2048)
#define NWQ  (2048 * 2048)
#define NWK  (512 * 2048)
#define NWV  (512 * 2048)
#define NWO  (2048 * 2048)

__global__ __launch_bounds__(256) void convert_kernel(
    const float* __restrict__ x,  const float* __restrict__ wq,
    const float* __restrict__ wk, const float* __restrict__ wv,
    const float* __restrict__ wo)
{
    const long long total = (long long)NX + NWQ + NWK + NWV + NWO;
    long long i = (long long)blockIdx.x * blockDim.x + threadIdx.x;
    const long long stride = (long long)gridDim.x * blockDim.x;
    for (; i < total; i += stride) {
        float v; __nv_bfloat16 *dh, *dl; long long off;
        if (i < NX)                        { off = i;      v = x[off];  dh = g_x_hi;  dl = g_x_lo; }
        else if (i < NX + NWQ)             { off = i - NX; v = wq[off]; dh = g_w_hi;  dl = g_w_lo; }
        else if (i < NX + NWQ + NWK)       { long long o = i - NX - NWQ; v = wk[o];
                                             off = (long long)2048 * 2048 + o;       dh = g_w_hi;  dl = g_w_lo; }
        else if (i < NX + NWQ + NWK + NWV) { long long o = i - NX - NWQ - NWK; v = wv[o];
                                             off = (long long)2560 * 2048 + o;       dh = g_w_hi;  dl = g_w_lo; }
        else                               { off = i - NX - NWQ - NWK - NWV; v = wo[off];
                                             dh = g_wo_hi; dl = g_wo_lo; }
        __nv_bfloat16 h = __float2bfloat16(v);
        __nv_bfloat16 l = __float2bfloat16(v - __bfloat162float(h));
        dh[off] = h; dl[off] = l;
    }
}

// ---------------------------------------------------------------------------
// Split-bf16 mma.sync GEMM: 128x128x32 CTA tile, 3-stage cp.async pipeline,
// 8 warps (2m x 4n), warp tile 64x32, m16n8k16 HMMA.
// mode 0: C = x @ [wq;wk;wv]^T + RoPE epilogue -> g_Q/g_K/g_V
// mode 1: C = attn_out @ wo^T -> out
// ---------------------------------------------------------------------------
#define STAGES     3
#define STAGE_BYTES 32768                  // 4 tiles x 8KB
#define GEMM_SMEM  (STAGES * STAGE_BYTES)
#define NIT        (D_MODEL / 32)          // 64

__global__ __launch_bounds__(256) void gemm_kernel(
    int mode, const float* __restrict__ fcos, const float* __restrict__ fsin,
    float* __restrict__ out)
{
    extern __shared__ char smem[];
    const uint32_t sb = smem_u32(smem);
    const int tid  = threadIdx.x;
    const int wid  = tid >> 5;
    const int lane = tid & 31;
    const int wm   = wid & 1;      // 0..1
    const int wn   = wid >> 1;     // 0..3

    const int n0 = blockIdx.x * 128;
    const int m0 = blockIdx.y * 128;

    const __nv_bfloat16 *Ahi, *Alo, *Bhi, *Blo;
    if (mode == 0) { Ahi = g_x_hi; Alo = g_x_lo; Bhi = g_w_hi;  Blo = g_w_lo; }
    else           { Ahi = g_a_hi; Alo = g_a_lo; Bhi = g_wo_hi; Blo = g_wo_lo; }

    // issue one stage of async copies: 4 tiles, 2 chunks of 16B per thread each
    auto issue_stage = [&](int stage, int k0) {
        const uint32_t stg = sb + stage * STAGE_BYTES;
        #pragma unroll
        for (int c = 0; c < 2; c++) {
            const int j = tid + 256 * c;
            const int row = j >> 2;
            const int ch  = j & 3;
            const uint32_t so = tile_off(row, ch);
            const size_t ga = (size_t)(m0 + row) * D_MODEL + k0 + ch * 8;
            const size_t gb = (size_t)(n0 + row) * D_MODEL + k0 + ch * 8;
            cp16(stg + so,         Ahi + ga);
            cp16(stg + 8192 + so,  Alo + ga);
            cp16(stg + 16384 + so, Bhi + gb);
            cp16(stg + 24576 + so, Blo + gb);
        }
    };

    float acc[4][4][4];
    #pragma unroll
    for (int i = 0; i < 4; i++)
        #pragma unroll
        for (int j = 0; j < 4; j++)
            #pragma unroll
            for (int r = 0; r < 4; r++) acc[i][j][r] = 0.0f;

    issue_stage(0, 0);  CP_COMMIT();
    issue_stage(1, 32); CP_COMMIT();

    // ldmatrix lane addressing (constant across iterations)
    const int a_row = wm * 64 + ((lane >> 3) & 1) * 8 + (lane & 7); // + mi*16
    const int a_chd = (lane >> 4);                                   // chunk delta
    const int b_row = wn * 32 + (lane >> 4) * 8 + (lane & 7);        // + bi*16
    const int b_chd = ((lane >> 3) & 1);

    for (int it = 0; it < NIT; it++) {
        CP_WAIT1();
        __syncthreads();
        const uint32_t stg = sb + (it % STAGES) * STAGE_BYTES;

        #pragma unroll
        for (int ks = 0; ks < 2; ks++) {
            const int kc = ks * 2;
            uint32_t ahi[4][4], alo[4][4];
            #pragma unroll
            for (int mi = 0; mi < 4; mi++) {
                const uint32_t off = tile_off(a_row + mi * 16, kc + a_chd);
                ldmx4(ahi[mi], stg + off);
                ldmx4(alo[mi], stg + 8192 + off);
            }
            uint32_t bhi[2][4], blo[2][4];
            #pragma unroll
            for (int bi = 0; bi < 2; bi++) {
                const uint32_t off = tile_off(b_row + bi * 16, kc + b_chd);
                ldmx4(bhi[bi], stg + 16384 + off);
                ldmx4(blo[bi], stg + 24576 + off);
            }
            #pragma unroll
            for (int mi = 0; mi < 4; mi++)
                #pragma unroll
                for (int ni = 0; ni < 4; ni++) {
                    const int bi = ni >> 1, rb = (ni & 1) * 2;
                    mma16816(acc[mi][ni], ahi[mi], bhi[bi][rb], bhi[bi][rb + 1]);
                    mma16816(acc[mi][ni], ahi[mi], blo[bi][rb], blo[bi][rb + 1]);
                    mma16816(acc[mi][ni], alo[mi], bhi[bi][rb], bhi[bi][rb + 1]);
                }
        }

        if (it + 2 < NIT) issue_stage((it + 2) % STAGES, (it + 2) * 32);
        CP_COMMIT();
    }

    // ---------------- epilogue ----------------
    // C frag: c0 -> (r, c), c1 -> (r, c+1), c2 -> (r+8, c), c3 -> (r+8, c+1)
    // where r = lane>>2, c = 2*(lane&3); columns (c, c+1) are the RoPE pair.
    const int mbase = m0 + wm * 64 + (lane >> 2);
    const int ncol  = 2 * (lane & 3);

    if (mode == 1) {
        #pragma unroll
        for (int mi = 0; mi < 4; mi++) {
            #pragma unroll
            for (int ni = 0; ni < 4; ni++) {
                const int n = n0 + wn * 32 + ni * 8 + ncol;
                const int m = mbase + mi * 16;
                float2 v0 = make_float2(acc[mi][ni][0], acc[mi][ni][1]);
                float2 v1 = make_float2(acc[mi][ni][2], acc[mi][ni][3]);
                *(float2*)(out + (size_t)m * D_MODEL + n)       = v0;
                *(float2*)(out + (size_t)(m + 8) * D_MODEL + n) = v1;
            }
        }
    } else {
        int kind, nb0;
        if (n0 < 2048)      { kind = 0; nb0 = n0; }
        else if (n0 < 2560) { kind = 1; nb0 = n0 - 2048; }
        else                { kind = 2; nb0 = n0 - 2560; }
        #pragma unroll
        for (int ni = 0; ni < 4; ni++) {
            const int nb = nb0 + wn * 32 + ni * 8 + ncol;
            const int h = nb >> 6;
            const int d = nb & 63;
            float cc = 0.f, ss = 0.f;
            if (kind != 2) {
                const int p = d >> 1;
                cc = fcos[h * (HD / 2) + p];
                ss = fsin[h * (HD / 2) + p];
            }
            #pragma unroll
            for (int mi = 0; mi < 4; mi++) {
                #pragma unroll
                for (int half = 0; half < 2; half++) {
                    const int m = mbase + mi * 16 + half * 8;
                    const int bb = m >> 10;
                    const int s  = m & 1023;
                    const float v0 = acc[mi][ni][half * 2 + 0];
                    const float v1 = acc[mi][ni][half * 2 + 1];
                    if (kind == 2) {
                        float* dst = g_V + ((size_t)(bb * NKV + h) * SEQ + s) * HD + d;
                        *(float2*)dst = make_float2(v0, v1);
                    } else {
                        const float o0 = v0 * cc - v1 * ss;
                        const float o1 = v0 * ss + v1 * cc;
                        float* dst = (kind == 0)
                            ? g_Q + ((size_t)(bb * NH  + h) * SEQ + s) * HD + d
                            : g_K + ((size_t)(bb * NKV + h) * SEQ + s) * HD + d;
                        *(float2*)dst = make_float2(o0, o1);
                    }
                }
            }
        }
    }
}

// ---------------------------------------------------------------------------
// Flash-style causal attention (fp32), epilogue writes split-bf16.
// ---------------------------------------------------------------------------
#define ATT_STR 68
#define ATT_SMEM (3 * 64 * ATT_STR * 4)

__global__ __launch_bounds__(256) void attn_kernel()
{
    extern __shared__ float sm[];
    float* Ks = sm;
    float* Vs = sm + 64 * ATT_STR;
    float* Ps = sm + 2 * 64 * ATT_STR;

    const int tid   = threadIdx.x;
    const int qtile = blockIdx.x;
    const int h     = blockIdx.y;
    const int b     = blockIdx.z;
    const int hk    = h >> 2;

    const int qr = tid >> 2;
    const int qu = tid & 3;
    const int qgl = qtile * 64 + qr;

    {
        const float* src = g_Q + ((size_t)(b * NH + h) * SEQ + qtile * 64) * HD;
        #pragma unroll
        for (int i = 0; i < 4; i++) {
            int f4 = tid + 256 * i;
            int row = f4 >> 4;
            int col = (f4 & 15) * 4;
            *(float4*)&Ps[row * ATT_STR + col] = ((const float4*)src)[f4];
        }
    }
    __syncthreads();
    float q_reg[64];
    #pragma unroll
    for (int d4 = 0; d4 < 16; d4++) {
        float4 v = *(const float4*)&Ps[qr * ATT_STR + d4 * 4];
        q_reg[d4 * 4 + 0] = v.x; q_reg[d4 * 4 + 1] = v.y;
        q_reg[d4 * 4 + 2] = v.z; q_reg[d4 * 4 + 3] = v.w;
    }
    __syncthreads();

    float acc[16];
    #pragma unroll
    for (int j = 0; j < 16; j++) acc[j] = 0.0f;
    float mrow = -INFINITY;
    float lrow = 0.0f;

    const int ntiles = qtile + 1;
    const float* kbase = g_K + ((size_t)(b * NKV + hk) * SEQ) * HD;
    const float* vbase = g_V + ((size_t)(b * NKV + hk) * SEQ) * HD;

    for (int t = 0; t < ntiles; t++) {
        {
            const float* ksrc = kbase + (size_t)t * 64 * HD;
            const float* vsrc = vbase + (size_t)t * 64 * HD;
            #pragma unroll
            for (int i = 0; i < 4; i++) {
                int f4 = tid + 256 * i;
                int row = f4 >> 4;
                int col = (f4 & 15) * 4;
                *(float4*)&Ks[row * ATT_STR + col] = ((const float4*)ksrc)[f4];
                *(float4*)&Vs[row * ATT_STR + col] = ((const float4*)vsrc)[f4];
            }
        }
        __syncthreads();

        float tmax = -INFINITY;
        for (int kk = 0; kk < 16; kk++) {
            const int k = qu * 16 + kk;
            const float4* kr4 = (const float4*)&Ks[k * ATT_STR];
            float s = 0.0f;
            #pragma unroll
            for (int d4 = 0; d4 < 16; d4++) {
                float4 kv = kr4[d4];
                s = fmaf(q_reg[d4 * 4 + 0], kv.x, s);
                s = fmaf(q_reg[d4 * 4 + 1], kv.y, s);
                s = fmaf(q_reg[d4 * 4 + 2], kv.z, s);
                s = fmaf(q_reg[d4 * 4 + 3], kv.w, s);
            }
            s *= 0.125f;
            const int kgl = t * 64 + k;
            if (kgl > qgl) s = -INFINITY;
            Ps[qr * ATT_STR + k] = s;
            tmax = fmaxf(tmax, s);
        }
        tmax = fmaxf(tmax, __shfl_xor_sync(0xFFFFFFFFu, tmax, 1));
        tmax = fmaxf(tmax, __shfl_xor_sync(0xFFFFFFFFu, tmax, 2));

        const float mnew = fmaxf(mrow, tmax);
        const float corr = __expf(mrow - mnew);

        float psum = 0.0f;
        for (int kk = 0; kk < 16; kk++) {
            const int k = qu * 16 + kk;
            float p = __expf(Ps[qr * ATT_STR + k] - mnew);
            Ps[qr * ATT_STR + k] = p;
            psum += p;
        }
        psum += __shfl_xor_sync(0xFFFFFFFFu, psum, 1);
        psum += __shfl_xor_sync(0xFFFFFFFFu, psum, 2);

        lrow = lrow * corr + psum;
        mrow = mnew;
        #pragma unroll
        for (int j = 0; j < 16; j++) acc[j] *= corr;
        __syncthreads();

        for (int k = 0; k < 64; k++) {
            const float p = Ps[qr * ATT_STR + k];
            const float4* vr = (const float4*)&Vs[k * ATT_STR + qu * 16];
            #pragma unroll
            for (int j4 = 0; j4 < 4; j4++) {
                float4 v = vr[j4];
                acc[j4 * 4 + 0] = fmaf(p, v.x, acc[j4 * 4 + 0]);
                acc[j4 * 4 + 1] = fmaf(p, v.y, acc[j4 * 4 + 1]);
                acc[j4 * 4 + 2] = fmaf(p, v.z, acc[j4 * 4 + 2]);
                acc[j4 * 4 + 3] = fmaf(p, v.w, acc[j4 * 4 + 3]);
            }
        }
        __syncthreads();
    }

    const float inv = 1.0f / lrow;
    const size_t base = ((size_t)(b * SEQ + qgl)) * D_MODEL + h * HD + qu * 16;
    #pragma unroll
    for (int j = 0; j < 16; j++) {
        float o = acc[j] * inv;
        __nv_bfloat16 hb = __float2bfloat16(o);
        __nv_bfloat16 lb = __float2bfloat16(o - __bfloat162float(hb));
        g_a_hi[base + j] = hb;
        g_a_lo[base + j] = lb;
    }
}

// ---------------------------------------------------------------------------
// Launch
// ---------------------------------------------------------------------------
extern "C" void kernel_launch(void* const* d_in, const int* in_sizes, int n_in,
                              void* d_out, int out_size)
{
    (void)in_sizes; (void)n_in; (void)out_size;
    const float* x    = (const float*)d_in[0];
    const float* fcos = (const float*)d_in[1];
    const float* fsin = (const float*)d_in[2];
    // d_in[3] = mask (causal; computed by predicate)
    const float* wq   = (const float*)d_in[4];
    const float* wk   = (const float*)d_in[5];
    const float* wv   = (const float*)d_in[6];
    const float* wo   = (const float*)d_in[7];
    float* out = (float*)d_out;

    cudaFuncSetAttribute(gemm_kernel,
                         cudaFuncAttributeMaxDynamicSharedMemorySize, GEMM_SMEM);
    cudaFuncSetAttribute(attn_kernel,
                         cudaFuncAttributeMaxDynamicSharedMemorySize, ATT_SMEM);

    convert_kernel<<<4096, 256>>>(x, wq, wk, wv, wo);

    dim3 gq(3072 / 128, 4096 / 128);
    gemm_kernel<<<gq, 256, GEMM_SMEM>>>(0, fcos, fsin, nullptr);

    dim3 ga(SEQ / 64, NH, BATCH);
    attn_kernel<<<ga, 256, ATT_SMEM>>>();

    dim3 go(2048 / 128, 4096 / 128);
    gemm_kernel<<<go, 256, GEMM_SMEM>>>(1, nullptr, nullptr, out);
}

// round 5
// speedup vs baseline: 5.6970x; 4.1415x over previous
#include <cuda_runtime.h>
#include <cuda_bf16.h>
#include <math.h>
#include <stdint.h>

#define D_MODEL 2048
#define SEQ     1024
#define BATCH   4
#define NH      32
#define NKV     8
#define HD      64

// ---------------------------------------------------------------------------
// Device-global scratch (no runtime allocation allowed)
// ---------------------------------------------------------------------------
// split-bf16 GEMM operands
__device__ __nv_bfloat16 g_x_hi[4096 * 2048], g_x_lo[4096 * 2048];
__device__ __nv_bfloat16 g_w_hi[3072 * 2048], g_w_lo[3072 * 2048];   // [wq;wk;wv]
__device__ __nv_bfloat16 g_wo_hi[2048 * 2048], g_wo_lo[2048 * 2048];
__device__ __nv_bfloat16 g_a_hi[4096 * 2048], g_a_lo[4096 * 2048];   // attn out

// split-bf16 Q/K/V (post-RoPE), layouts (B,H,S,HD) / (B,KV,S,HD)
__device__ __nv_bfloat16 g_Qhi[BATCH * NH  * SEQ * HD], g_Qlo[BATCH * NH  * SEQ * HD];
__device__ __nv_bfloat16 g_Khi[BATCH * NKV * SEQ * HD], g_Klo[BATCH * NKV * SEQ * HD];
__device__ __nv_bfloat16 g_Vhi[BATCH * NKV * SEQ * HD], g_Vlo[BATCH * NKV * SEQ * HD];

// ---------------------------------------------------------------------------
// helpers
// ---------------------------------------------------------------------------
__device__ __forceinline__ uint32_t smem_u32(const void* p) {
    uint32_t a;
    asm("{ .reg .u64 t; cvta.to.shared.u64 t, %1; cvt.u32.u64 %0, t; }"
        : "=r"(a) : "l"(p));
    return a;
}
__device__ __forceinline__ uint32_t tile_off(int row, int chunk) {
    return (uint32_t)(((row >> 1) * 128) + ((row & 1) * 64) +
                      (((chunk ^ ((row >> 1) & 3))) << 4));
}
__device__ __forceinline__ void cp16(uint32_t dst, const __nv_bfloat16* src) {
    asm volatile("cp.async.cg.shared.global [%0], [%1], 16;"
                 :: "r"(dst), "l"(__cvta_generic_to_global(src)));
}
#define CP_COMMIT() asm volatile("cp.async.commit_group;" ::: "memory")
#define CP_WAIT1()  asm volatile("cp.async.wait_group 1;" ::: "memory")
#define CP_WAIT0()  asm volatile("cp.async.wait_group 0;" ::: "memory")

__device__ __forceinline__ void ldmx4(uint32_t* r, uint32_t addr) {
    asm volatile("ldmatrix.sync.aligned.m8n8.x4.shared.b16 {%0,%1,%2,%3}, [%4];"
                 : "=r"(r[0]), "=r"(r[1]), "=r"(r[2]), "=r"(r[3]) : "r"(addr));
}
__device__ __forceinline__ void ldmx4t(uint32_t* r, uint32_t addr) {
    asm volatile("ldmatrix.sync.aligned.m8n8.x4.trans.shared.b16 {%0,%1,%2,%3}, [%4];"
                 : "=r"(r[0]), "=r"(r[1]), "=r"(r[2]), "=r"(r[3]) : "r"(addr));
}
__device__ __forceinline__ void mma16816(float* c, const uint32_t* a,
                                         uint32_t b0, uint32_t b1) {
    asm volatile(
        "mma.sync.aligned.m16n8k16.row.col.f32.bf16.bf16.f32 "
        "{%0,%1,%2,%3}, {%4,%5,%6,%7}, {%8,%9}, {%0,%1,%2,%3};"
        : "+f"(c[0]), "+f"(c[1]), "+f"(c[2]), "+f"(c[3])
        : "r"(a[0]), "r"(a[1]), "r"(a[2]), "r"(a[3]), "r"(b0), "r"(b1));
}

__device__ __forceinline__ uint16_t bfbits(__nv_bfloat16 h) {
    return *reinterpret_cast<uint16_t*>(&h);
}
// split (x,y) fp32 pair into packed-bf16 hi word and lo word
__device__ __forceinline__ void split2(float x, float y, uint32_t& H, uint32_t& L) {
    __nv_bfloat16 hx = __float2bfloat16(x), hy = __float2bfloat16(y);
    __nv_bfloat16 lx = __float2bfloat16(x - __bfloat162float(hx));
    __nv_bfloat16 ly = __float2bfloat16(y - __bfloat162float(hy));
    H = ((uint32_t)bfbits(hy) << 16) | bfbits(hx);
    L = ((uint32_t)bfbits(ly) << 16) | bfbits(lx);
}

// ---------------------------------------------------------------------------
// fp32 -> (hi, lo) bf16 split conversion of all GEMM operands
// ---------------------------------------------------------------------------
#define NX   (4096 * 2048)
#define NWQ  (2048 * 2048)
#define NWK  (512 * 2048)
#define NWV  (512 * 2048)
#define NWO  (2048 * 2048)

__global__ __launch_bounds__(256) void convert_kernel(
    const float* __restrict__ x,  const float* __restrict__ wq,
    const float* __restrict__ wk, const float* __restrict__ wv,
    const float* __restrict__ wo)
{
    const long long total = (long long)NX + NWQ + NWK + NWV + NWO;
    long long i = (long long)blockIdx.x * blockDim.x + threadIdx.x;
    const long long stride = (long long)gridDim.x * blockDim.x;
    for (; i < total; i += stride) {
        float v; __nv_bfloat16 *dh, *dl; long long off;
        if (i < NX)                        { off = i;      v = x[off];  dh = g_x_hi;  dl = g_x_lo; }
        else if (i < NX + NWQ)             { off = i - NX; v = wq[off]; dh = g_w_hi;  dl = g_w_lo; }
        else if (i < NX + NWQ + NWK)       { long long o = i - NX - NWQ; v = wk[o];
                                             off = (long long)2048 * 2048 + o;       dh = g_w_hi;  dl = g_w_lo; }
        else if (i < NX + NWQ + NWK + NWV) { long long o = i - NX - NWQ - NWK; v = wv[o];
                                             off = (long long)2560 * 2048 + o;       dh = g_w_hi;  dl = g_w_lo; }
        else                               { off = i - NX - NWQ - NWK - NWV; v = wo[off];
                                             dh = g_wo_hi; dl = g_wo_lo; }
        __nv_bfloat16 h = __float2bfloat16(v);
        __nv_bfloat16 l = __float2bfloat16(v - __bfloat162float(h));
        dh[off] = h; dl[off] = l;
    }
}

// ---------------------------------------------------------------------------
// Split-bf16 mma.sync GEMM: 128x128x32 CTA tile, 3-stage cp.async pipeline.
// mode 0: C = x @ [wq;wk;wv]^T + RoPE epilogue -> split-bf16 g_Q/g_K/g_V
// mode 1: C = attn_out @ wo^T -> out (fp32)
// ---------------------------------------------------------------------------
#define STAGES     3
#define STAGE_BYTES 32768
#define GEMM_SMEM  (STAGES * STAGE_BYTES)
#define NIT        (D_MODEL / 32)

__global__ __launch_bounds__(256) void gemm_kernel(
    int mode, const float* __restrict__ fcos, const float* __restrict__ fsin,
    float* __restrict__ out)
{
    extern __shared__ char smem[];
    const uint32_t sb = smem_u32(smem);
    const int tid  = threadIdx.x;
    const int wid  = tid >> 5;
    const int lane = tid & 31;
    const int wm   = wid & 1;
    const int wn   = wid >> 1;

    const int n0 = blockIdx.x * 128;
    const int m0 = blockIdx.y * 128;

    const __nv_bfloat16 *Ahi, *Alo, *Bhi, *Blo;
    if (mode == 0) { Ahi = g_x_hi; Alo = g_x_lo; Bhi = g_w_hi;  Blo = g_w_lo; }
    else           { Ahi = g_a_hi; Alo = g_a_lo; Bhi = g_wo_hi; Blo = g_wo_lo; }

    auto issue_stage = [&](int stage, int k0) {
        const uint32_t stg = sb + stage * STAGE_BYTES;
        #pragma unroll
        for (int c = 0; c < 2; c++) {
            const int j = tid + 256 * c;
            const int row = j >> 2;
            const int ch  = j & 3;
            const uint32_t so = tile_off(row, ch);
            const size_t ga = (size_t)(m0 + row) * D_MODEL + k0 + ch * 8;
            const size_t gb = (size_t)(n0 + row) * D_MODEL + k0 + ch * 8;
            cp16(stg + so,         Ahi + ga);
            cp16(stg + 8192 + so,  Alo + ga);
            cp16(stg + 16384 + so, Bhi + gb);
            cp16(stg + 24576 + so, Blo + gb);
        }
    };

    float acc[4][4][4];
    #pragma unroll
    for (int i = 0; i < 4; i++)
        #pragma unroll
        for (int j = 0; j < 4; j++)
            #pragma unroll
            for (int r = 0; r < 4; r++) acc[i][j][r] = 0.0f;

    issue_stage(0, 0);  CP_COMMIT();
    issue_stage(1, 32); CP_COMMIT();

    const int a_row = wm * 64 + ((lane >> 3) & 1) * 8 + (lane & 7);
    const int a_chd = (lane >> 4);
    const int b_row = wn * 32 + (lane >> 4) * 8 + (lane & 7);
    const int b_chd = ((lane >> 3) & 1);

    for (int it = 0; it < NIT; it++) {
        CP_WAIT1();
        __syncthreads();
        const uint32_t stg = sb + (it % STAGES) * STAGE_BYTES;

        #pragma unroll
        for (int ks = 0; ks < 2; ks++) {
            const int kc = ks * 2;
            uint32_t ahi[4][4], alo[4][4];
            #pragma unroll
            for (int mi = 0; mi < 4; mi++) {
                const uint32_t off = tile_off(a_row + mi * 16, kc + a_chd);
                ldmx4(ahi[mi], stg + off);
                ldmx4(alo[mi], stg + 8192 + off);
            }
            uint32_t bhi[2][4], blo[2][4];
            #pragma unroll
            for (int bi = 0; bi < 2; bi++) {
                const uint32_t off = tile_off(b_row + bi * 16, kc + b_chd);
                ldmx4(bhi[bi], stg + 16384 + off);
                ldmx4(blo[bi], stg + 24576 + off);
            }
            #pragma unroll
            for (int mi = 0; mi < 4; mi++)
                #pragma unroll
                for (int ni = 0; ni < 4; ni++) {
                    const int bi = ni >> 1, rb = (ni & 1) * 2;
                    mma16816(acc[mi][ni], ahi[mi], bhi[bi][rb], bhi[bi][rb + 1]);
                    mma16816(acc[mi][ni], ahi[mi], blo[bi][rb], blo[bi][rb + 1]);
                    mma16816(acc[mi][ni], alo[mi], bhi[bi][rb], bhi[bi][rb + 1]);
                }
        }

        if (it + 2 < NIT) issue_stage((it + 2) % STAGES, (it + 2) * 32);
        CP_COMMIT();
    }

    const int mbase = m0 + wm * 64 + (lane >> 2);
    const int ncol  = 2 * (lane & 3);

    if (mode == 1) {
        #pragma unroll
        for (int mi = 0; mi < 4; mi++) {
            #pragma unroll
            for (int ni = 0; ni < 4; ni++) {
                const int n = n0 + wn * 32 + ni * 8 + ncol;
                const int m = mbase + mi * 16;
                *(float2*)(out + (size_t)m * D_MODEL + n) =
                    make_float2(acc[mi][ni][0], acc[mi][ni][1]);
                *(float2*)(out + (size_t)(m + 8) * D_MODEL + n) =
                    make_float2(acc[mi][ni][2], acc[mi][ni][3]);
            }
        }
    } else {
        int kind, nb0;
        if (n0 < 2048)      { kind = 0; nb0 = n0; }
        else if (n0 < 2560) { kind = 1; nb0 = n0 - 2048; }
        else                { kind = 2; nb0 = n0 - 2560; }
        #pragma unroll
        for (int ni = 0; ni < 4; ni++) {
            const int nb = nb0 + wn * 32 + ni * 8 + ncol;
            const int h = nb >> 6;
            const int d = nb & 63;
            float cc = 0.f, ss = 0.f;
            if (kind != 2) {
                const int p = d >> 1;
                cc = fcos[h * (HD / 2) + p];
                ss = fsin[h * (HD / 2) + p];
            }
            #pragma unroll
            for (int mi = 0; mi < 4; mi++) {
                #pragma unroll
                for (int half = 0; half < 2; half++) {
                    const int m = mbase + mi * 16 + half * 8;
                    const int bb = m >> 10;
                    const int s  = m & 1023;
                    const float v0 = acc[mi][ni][half * 2 + 0];
                    const float v1 = acc[mi][ni][half * 2 + 1];
                    uint32_t H, L;
                    if (kind == 2) {
                        const size_t idx = ((size_t)(bb * NKV + h) * SEQ + s) * HD + d;
                        split2(v0, v1, H, L);
                        *(uint32_t*)(g_Vhi + idx) = H;
                        *(uint32_t*)(g_Vlo + idx) = L;
                    } else {
                        const float o0 = v0 * cc - v1 * ss;
                        const float o1 = v0 * ss + v1 * cc;
                        split2(o0, o1, H, L);
                        if (kind == 0) {
                            const size_t idx = ((size_t)(bb * NH + h) * SEQ + s) * HD + d;
                            *(uint32_t*)(g_Qhi + idx) = H;
                            *(uint32_t*)(g_Qlo + idx) = L;
                        } else {
                            const size_t idx = ((size_t)(bb * NKV + h) * SEQ + s) * HD + d;
                            *(uint32_t*)(g_Khi + idx) = H;
                            *(uint32_t*)(g_Klo + idx) = L;
                        }
                    }
                }
            }
        }
    }
}

// ---------------------------------------------------------------------------
// Tensor-core flash attention (split-bf16, fp32 softmax).
// CTA: 128 q rows x one head. 8 warps x 16 rows. KV tiles of 64, 3-stage pipe.
// SMEM tile rows padded to 72 bf16 (144B) -> conflict-free ldmatrix.
// ---------------------------------------------------------------------------
#define TROW      144                    // bytes per padded tile row
#define TILE_B    (64 * TROW)            // 9216 bytes per 64x64 tile
#define ASTAGE    (4 * TILE_B)           // Khi,Klo,Vhi,Vlo = 36864
#define ATT_SMEM  (3 * ASTAGE)           // 110592

__global__ __launch_bounds__(256) void attn_kernel()
{
    extern __shared__ char smem[];
    const uint32_t sb = smem_u32(smem);
    const int tid  = threadIdx.x;
    const int wid  = tid >> 5;
    const int lane = tid & 31;

    const int qt = (int)(gridDim.x - 1 - blockIdx.x);   // big tiles first
    const int h  = blockIdx.y;
    const int bz = blockIdx.z;
    const int hk = h >> 2;

    // ---------------- Q tile -> registers ----------------
    {
        const size_t qbase = ((size_t)(bz * NH + h) * SEQ + (size_t)qt * 128) * HD;
        #pragma unroll
        for (int i = 0; i < 4; i++) {
            const int j = tid + 256 * i;       // 0..1023
            const int row = j >> 3;
            const int ch  = j & 7;
            const uint32_t dst = sb + row * TROW + ch * 16;
            cp16(dst,         g_Qhi + qbase + row * HD + ch * 8);
            cp16(dst + 18432, g_Qlo + qbase + row * HD + ch * 8);
        }
    }
    CP_COMMIT();
    CP_WAIT0();
    __syncthreads();

    uint32_t qh[4][4], ql[4][4];
    {
        const int qrow = wid * 16 + (lane & 7) + ((lane >> 3) & 1) * 8;
        const int qcol = (lane >> 4) * 8;
        #pragma unroll
        for (int kt = 0; kt < 4; kt++) {
            const uint32_t addr = sb + qrow * TROW + (kt * 16 + qcol) * 2;
            ldmx4(qh[kt], addr);
            ldmx4(ql[kt], addr + 18432);
        }
    }
    __syncthreads();   // smem free for K/V pipeline

    const size_t kvbase = ((size_t)(bz * NKV + hk) * SEQ) * HD;
    auto issue_kv = [&](int t, int stage) {
        const uint32_t stg = sb + stage * ASTAGE;
        const size_t gb = kvbase + (size_t)t * 64 * HD;
        #pragma unroll
        for (int i = 0; i < 2; i++) {
            const int j = tid + 256 * i;       // 0..511
            const int row = j >> 3;
            const int ch  = j & 7;
            const uint32_t off = row * TROW + ch * 16;
            const size_t g = gb + row * HD + ch * 8;
            cp16(stg + off,              g_Khi + g);
            cp16(stg + TILE_B + off,     g_Klo + g);
            cp16(stg + 2 * TILE_B + off, g_Vhi + g);
            cp16(stg + 3 * TILE_B + off, g_Vlo + g);
        }
    };

    const int nt = 2 * (qt + 1);
    issue_kv(0, 0); CP_COMMIT();
    issue_kv(1, 1); CP_COMMIT();

    // per-lane state: two rows (ra, ra+8)
    const int ra   = wid * 16 + (lane >> 2);
    const int qgl_a = qt * 128 + ra;
    const int qgl_b = qgl_a + 8;
    const int lane_c = 2 * (lane & 3);

    float acc[8][4];
    #pragma unroll
    for (int i = 0; i < 8; i++)
        #pragma unroll
        for (int r = 0; r < 4; r++) acc[i][r] = 0.0f;
    float m_a = -INFINITY, m_b = -INFINITY, l_a = 0.0f, l_b = 0.0f;

    const uint32_t kb_row = (lane >> 4) * 8 + (lane & 7);
    const uint32_t kb_col = ((lane >> 3) & 1) * 8;
    const uint32_t vb_row = (lane & 7) + ((lane >> 3) & 1) * 8;
    const uint32_t vb_col = (lane >> 4) * 8;

    for (int t = 0; t < nt; t++) {
        CP_WAIT1();
        __syncthreads();
        if (t + 2 < nt) issue_kv(t + 2, (t + 2) % 3);
        CP_COMMIT();

        const uint32_t stK = sb + (t % 3) * ASTAGE;
        const uint32_t stV = stK + 2 * TILE_B;

        // ---- scores S = Q K^T (3-term split) ----
        float sfr[8][4];
        #pragma unroll
        for (int i = 0; i < 8; i++)
            #pragma unroll
            for (int r = 0; r < 4; r++) sfr[i][r] = 0.0f;

        #pragma unroll
        for (int kt = 0; kt < 4; kt++) {
            #pragma unroll
            for (int nip = 0; nip < 4; nip++) {
                const uint32_t addr = stK + (nip * 16 + kb_row) * TROW
                                          + (kt * 16 + kb_col) * 2;
                uint32_t kh[4], kl[4];
                ldmx4(kh, addr);
                ldmx4(kl, addr + TILE_B);
                mma16816(sfr[2 * nip],     qh[kt], kh[0], kh[1]);
                mma16816(sfr[2 * nip],     qh[kt], kl[0], kl[1]);
                mma16816(sfr[2 * nip],     ql[kt], kh[0], kh[1]);
                mma16816(sfr[2 * nip + 1], qh[kt], kh[2], kh[3]);
                mma16816(sfr[2 * nip + 1], qh[kt], kl[2], kl[3]);
                mma16816(sfr[2 * nip + 1], ql[kt], kh[2], kh[3]);
            }
        }

        // ---- scale + causal mask + row max ----
        float mx_a = -INFINITY, mx_b = -INFINITY;
        #pragma unroll
        for (int ni = 0; ni < 8; ni++) {
            const int col0 = t * 64 + ni * 8 + lane_c;
            #pragma unroll
            for (int e = 0; e < 2; e++) {
                float va = sfr[ni][e] * 0.125f;
                float vb = sfr[ni][2 + e] * 0.125f;
                if (col0 + e > qgl_a) va = -INFINITY;
                if (col0 + e > qgl_b) vb = -INFINITY;
                sfr[ni][e] = va; sfr[ni][2 + e] = vb;
                mx_a = fmaxf(mx_a, va); mx_b = fmaxf(mx_b, vb);
            }
        }
        mx_a = fmaxf(mx_a, __shfl_xor_sync(0xFFFFFFFFu, mx_a, 1));
        mx_a = fmaxf(mx_a, __shfl_xor_sync(0xFFFFFFFFu, mx_a, 2));
        mx_b = fmaxf(mx_b, __shfl_xor_sync(0xFFFFFFFFu, mx_b, 1));
        mx_b = fmaxf(mx_b, __shfl_xor_sync(0xFFFFFFFFu, mx_b, 2));

        const float mn_a = fmaxf(m_a, mx_a);
        const float mn_b = fmaxf(m_b, mx_b);
        const float corr_a = __expf(m_a - mn_a);
        const float corr_b = __expf(m_b - mn_b);
        m_a = mn_a; m_b = mn_b;

        // ---- exponentiate + row sum ----
        float ps_a = 0.0f, ps_b = 0.0f;
        #pragma unroll
        for (int ni = 0; ni < 8; ni++) {
            #pragma unroll
            for (int e = 0; e < 2; e++) {
                float pa = __expf(sfr[ni][e] - mn_a);
                float pb = __expf(sfr[ni][2 + e] - mn_b);
                sfr[ni][e] = pa; sfr[ni][2 + e] = pb;
                ps_a += pa; ps_b += pb;
            }
        }
        ps_a += __shfl_xor_sync(0xFFFFFFFFu, ps_a, 1);
        ps_a += __shfl_xor_sync(0xFFFFFFFFu, ps_a, 2);
        ps_b += __shfl_xor_sync(0xFFFFFFFFu, ps_b, 1);
        ps_b += __shfl_xor_sync(0xFFFFFFFFu, ps_b, 2);
        l_a = l_a * corr_a + ps_a;
        l_b = l_b * corr_b + ps_b;

        #pragma unroll
        for (int i = 0; i < 8; i++) {
            acc[i][0] *= corr_a; acc[i][1] *= corr_a;
            acc[i][2] *= corr_b; acc[i][3] *= corr_b;
        }

        // ---- P @ V (P split hi/lo; V split hi/lo) ----
        #pragma unroll
        for (int kt = 0; kt < 4; kt++) {
            uint32_t ph[4], pl[4];
            split2(sfr[2 * kt][0],     sfr[2 * kt][1],     ph[0], pl[0]);
            split2(sfr[2 * kt][2],     sfr[2 * kt][3],     ph[1], pl[1]);
            split2(sfr[2 * kt + 1][0], sfr[2 * kt + 1][1], ph[2], pl[2]);
            split2(sfr[2 * kt + 1][2], sfr[2 * kt + 1][3], ph[3], pl[3]);
            #pragma unroll
            for (int ndp = 0; ndp < 4; ndp++) {
                const uint32_t addr = stV + (kt * 16 + vb_row) * TROW
                                          + (ndp * 16 + vb_col) * 2;
                uint32_t vh[4], vl[4];
                ldmx4t(vh, addr);
                ldmx4t(vl, addr + TILE_B);
                mma16816(acc[2 * ndp],     ph, vh[0], vh[1]);
                mma16816(acc[2 * ndp],     ph, vl[0], vl[1]);
                mma16816(acc[2 * ndp],     pl, vh[0], vh[1]);
                mma16816(acc[2 * ndp + 1], ph, vh[2], vh[3]);
                mma16816(acc[2 * ndp + 1], ph, vl[2], vl[3]);
                mma16816(acc[2 * ndp + 1], pl, vh[2], vh[3]);
            }
        }
        __syncthreads();
    }

    // ---------------- epilogue: normalize, split-bf16 store ----------------
    const float iva = 1.0f / l_a;
    const float ivb = 1.0f / l_b;
    const size_t rowA = ((size_t)bz * SEQ + qgl_a) * D_MODEL + h * HD + lane_c;
    const size_t rowB = ((size_t)bz * SEQ + qgl_b) * D_MODEL + h * HD + lane_c;
    #pragma unroll
    for (int nd = 0; nd < 8; nd++) {
        uint32_t H, L;
        split2(acc[nd][0] * iva, acc[nd][1] * iva, H, L);
        *(uint32_t*)(g_a_hi + rowA + nd * 8) = H;
        *(uint32_t*)(g_a_lo + rowA + nd * 8) = L;
        split2(acc[nd][2] * ivb, acc[nd][3] * ivb, H, L);
        *(uint32_t*)(g_a_hi + rowB + nd * 8) = H;
        *(uint32_t*)(g_a_lo + rowB + nd * 8) = L;
    }
}

// ---------------------------------------------------------------------------
// Launch
// ---------------------------------------------------------------------------
extern "C" void kernel_launch(void* const* d_in, const int* in_sizes, int n_in,
                              void* d_out, int out_size)
{
    (void)in_sizes; (void)n_in; (void)out_size;
    const float* x    = (const float*)d_in[0];
    const float* fcos = (const float*)d_in[1];
    const float* fsin = (const float*)d_in[2];
    // d_in[3] = mask (causal; computed by predicate)
    const float* wq   = (const float*)d_in[4];
    const float* wk   = (const float*)d_in[5];
    const float* wv   = (const float*)d_in[6];
    const float* wo   = (const float*)d_in[7];
    float* out = (float*)d_out;

    cudaFuncSetAttribute(gemm_kernel,
                         cudaFuncAttributeMaxDynamicSharedMemorySize, GEMM_SMEM);
    cudaFuncSetAttribute(attn_kernel,
                         cudaFuncAttributeMaxDynamicSharedMemorySize, ATT_SMEM);

    convert_kernel<<<4096, 256>>>(x, wq, wk, wv, wo);

    dim3 gq(3072 / 128, 4096 / 128);
    gemm_kernel<<<gq, 256, GEMM_SMEM>>>(0, fcos, fsin, nullptr);

    dim3 ga(SEQ / 128, NH, BATCH);
    attn_kernel<<<ga, 256, ATT_SMEM>>>();

    dim3 go(2048 / 128, 4096 / 128);
    gemm_kernel<<<go, 256, GEMM_SMEM>>>(1, nullptr, nullptr, out);
}